// round 5
// baseline (speedup 1.0000x reference)
#include <cuda_runtime.h>
#include <cuda_bf16.h>
#include <math.h>

// Problem dims
#define TT 512
#define BB 64
#define II 512
#define HH 512

// ---------------- device scratch ----------------
__device__ float g_xz[TT * BB];   // [t][b] includes zt_w_b
__device__ float g_xr[TT * BB];   // [t][b] includes rt_w_b

// ---------------- helpers ----------------
typedef unsigned long long ull;
union U64F2 { ull u; float2 f; };
union QU    { uint4 q; ull u[2]; };

__device__ __forceinline__ void fma2(ull& d, ull a, ull b) {
    asm("fma.rn.f32x2 %0, %1, %2, %0;" : "+l"(d) : "l"(a), "l"(b));
}
__device__ __forceinline__ ull pack2(float lo, float hi) {
    ull r; asm("mov.b64 %0, {%1, %2};" : "=l"(r) : "f"(lo), "f"(hi)); return r;
}
__device__ __forceinline__ float sigmoid_fast(float x) {
    float e, r;
    asm("ex2.approx.f32 %0, %1;" : "=f"(e) : "f"(-1.4426950408889634f * x));
    asm("rcp.approx.f32 %0, %1;" : "=f"(r) : "f"(1.0f + e));
    return r;
}
__device__ __forceinline__ float tanh_fast(float x) {
    float e, r;
    asm("ex2.approx.f32 %0, %1;" : "=f"(e) : "f"(-2.8853900817779268f * x));
    asm("rcp.approx.f32 %0, %1;" : "=f"(r) : "f"(1.0f + e));
    return fmaf(2.0f, r, -1.0f);
}
__device__ __forceinline__ unsigned smem_u32(const void* p) {
    return (unsigned)__cvta_generic_to_shared(p);
}

// ---------------- kernel 1: gate input projections xz, xr ----------------
__global__ void gate_pre_kernel(const float* __restrict__ in,
                                const float* __restrict__ zw, const float* __restrict__ zb,
                                const float* __restrict__ rw, const float* __restrict__ rb) {
    int row  = blockIdx.x * 8 + (threadIdx.x >> 5);
    int lane = threadIdx.x & 31;
    const float4* a4 = (const float4*)(in + (size_t)row * II);
    const float4* z4 = (const float4*)zw;
    const float4* r4 = (const float4*)rw;
    float az = 0.f, ar = 0.f;
#pragma unroll 4
    for (int i = lane; i < II / 4; i += 32) {
        float4 v = a4[i];
        float4 z = z4[i];
        float4 r = r4[i];
        az += v.x * z.x + v.y * z.y + v.z * z.z + v.w * z.w;
        ar += v.x * r.x + v.y * r.y + v.z * r.z + v.w * r.w;
    }
#pragma unroll
    for (int off = 16; off >= 1; off >>= 1) {
        az += __shfl_xor_sync(0xffffffffu, az, off);
        ar += __shfl_xor_sync(0xffffffffu, ar, off);
    }
    if (lane == 0) {
        g_xz[row] = az + zb[0];
        g_xr[row] = ar + rb[0];
    }
}

// ---------------- kernel 2: xn GEMM, k-pair f32x2, conflict-free smem ----
// C[m][n] = sum_k A[m,k] W[n,k] + bias[n].  M=32768, N=512, K=512.
// BM=128, BN=64, BK=32 (16 k-pairs). 256 threads.
// Thread (ncol=tid&7, mrow=tid>>3) computes 4 m x 8 n where the n-set is
// {2c,2c+1, 2c+16,2c+17, 2c+32,2c+33, 2c+48,2c+49} (c=ncol) so each W uint4
// load is a contiguous 128B warp-span (conflict-free).
__global__ __launch_bounds__(256) void xn_gemm_kernel(const float* __restrict__ A,
                                                      const float* __restrict__ W,
                                                      const float* __restrict__ bias,
                                                      float* __restrict__ C) {
    __shared__ ull As2[16][130];   // [kp][m]
    __shared__ ull Ws2[16][66];    // [kp][n]

    int tid  = threadIdx.x;
    int ncol = tid & 7;
    int mrow = tid >> 3;
    int nc2  = ncol * 2;
    int bm   = blockIdx.x * 128;
    int bn   = blockIdx.y * 64;

    ull acc[4][8];
#pragma unroll
    for (int i = 0; i < 4; i++)
#pragma unroll
        for (int j = 0; j < 8; j++) acc[i][j] = 0ull;

    const float4* A4 = (const float4*)A;
    const float4* W4 = (const float4*)W;

    float4 pa[4], pw[2];
#pragma unroll
    for (int q = 0; q < 4; q++) {
        int s = tid + q * 256;
        pa[q] = A4[(size_t)(bm + (s >> 3)) * 128 + (s & 7)];
    }
#pragma unroll
    for (int q = 0; q < 2; q++) {
        int s = tid + q * 256;
        pw[q] = W4[(size_t)(bn + (s >> 3)) * 128 + (s & 7)];
    }

    for (int blk = 0; blk < 16; blk++) {
#pragma unroll
        for (int q = 0; q < 4; q++) {
            int s = tid + q * 256;
            int m = s >> 3, f4 = s & 7;
            As2[f4 * 2][m]     = pack2(pa[q].x, pa[q].y);
            As2[f4 * 2 + 1][m] = pack2(pa[q].z, pa[q].w);
        }
#pragma unroll
        for (int q = 0; q < 2; q++) {
            int s = tid + q * 256;
            int n = s >> 3, f4 = s & 7;
            Ws2[f4 * 2][n]     = pack2(pw[q].x, pw[q].y);
            Ws2[f4 * 2 + 1][n] = pack2(pw[q].z, pw[q].w);
        }
        __syncthreads();
        if (blk < 15) {
            int kq = (blk + 1) * 8;
#pragma unroll
            for (int q = 0; q < 4; q++) {
                int s = tid + q * 256;
                pa[q] = A4[(size_t)(bm + (s >> 3)) * 128 + kq + (s & 7)];
            }
#pragma unroll
            for (int q = 0; q < 2; q++) {
                int s = tid + q * 256;
                pw[q] = W4[(size_t)(bn + (s >> 3)) * 128 + kq + (s & 7)];
            }
        }
#pragma unroll
        for (int kp = 0; kp < 16; kp++) {
            QU a01, a23, w0, w1, w2, w3;
            a01.q = *(const uint4*)&As2[kp][mrow * 4];
            a23.q = *(const uint4*)&As2[kp][mrow * 4 + 2];
            w0.q  = *(const uint4*)&Ws2[kp][nc2];
            w1.q  = *(const uint4*)&Ws2[kp][nc2 + 16];
            w2.q  = *(const uint4*)&Ws2[kp][nc2 + 32];
            w3.q  = *(const uint4*)&Ws2[kp][nc2 + 48];
            ull av[4] = {a01.u[0], a01.u[1], a23.u[0], a23.u[1]};
            ull wv[8] = {w0.u[0], w0.u[1], w1.u[0], w1.u[1],
                         w2.u[0], w2.u[1], w3.u[0], w3.u[1]};
#pragma unroll
            for (int i = 0; i < 4; i++)
#pragma unroll
                for (int j = 0; j < 8; j++) fma2(acc[i][j], av[i], wv[j]);
        }
        __syncthreads();
    }

    // bias for n-slots: pairs at nc2 + q*16
    float2 bq[4];
#pragma unroll
    for (int q = 0; q < 4; q++)
        bq[q] = ((const float2*)bias)[(bn >> 1) + (nc2 >> 1) + q * 8];

#pragma unroll
    for (int mi = 0; mi < 4; mi++) {
        int m = bm + mrow * 4 + mi;
#pragma unroll
        for (int q = 0; q < 4; q++) {
            U64F2 c0, c1;
            c0.u = acc[mi][q * 2];
            c1.u = acc[mi][q * 2 + 1];
            float2 o;
            o.x = c0.f.x + c0.f.y + bq[q].x;
            o.y = c1.f.x + c1.f.y + bq[q].y;
            ((float2*)C)[(size_t)m * 256 + (bn >> 1) + (nc2 >> 1) + q * 8] = o;
        }
    }
}

// ---------------- kernel 3: recurrent scan ----------------
// 16 clusters x 8 CTAs x 512 threads. Cluster g -> batches 4g..4g+3.
// CTA rank r -> h outputs [64r,64r+64). h exchanged via st.shared::cluster
// fan-out + barrier.cluster release/acquire (proven R3 sync). k-pair f32x2
// compute; next-step xn/xz/xr prefetched before the barrier.
#define WS_OFF   0                        // ull[256][64]  = 128KB
#define HP_OFF   131072                   // ull[2][1024]  = 16KB
#define PART_OFF (HP_OFF + 16384)         // float[16][4][64] = 16KB
#define ZRP_OFF  (PART_OFF + 16384)       // float[64]
#define ZUP_OFF  (ZRP_OFF + 256)          // ull[256]
#define RUP_OFF  (ZUP_OFF + 2048)         // ull[256]
#define HUB_OFF  (RUP_OFF + 2048)         // float[64]
#define SC_SMEM  (HUB_OFF + 256)

extern __shared__ char sc_smem[];

__global__ void __cluster_dims__(8, 1, 1) __launch_bounds__(512, 1)
scan_kernel(const float* __restrict__ hidden,
            const float* __restrict__ ztu_g, const float* __restrict__ ztub,
            const float* __restrict__ rtu_g, const float* __restrict__ rtub,
            const float* __restrict__ huw, const float* __restrict__ hub_g,
            float* __restrict__ out, int tail) {
    ull*   wS   = (ull*)(sc_smem + WS_OFF);
    ull*   hpb  = (ull*)(sc_smem + HP_OFF);
    float* part = (float*)(sc_smem + PART_OFF);
    float* zrpf = (float*)(sc_smem + ZRP_OFF);
    ull*   zup  = (ull*)(sc_smem + ZUP_OFF);
    ull*   rup  = (ull*)(sc_smem + RUP_OFF);
    float* hub  = (float*)(sc_smem + HUB_OFF);

    int tid    = threadIdx.x;
    int rank   = blockIdx.x & 7;
    int grp    = blockIdx.x >> 3;
    int jjbase = rank * 64;

    // -------- prologue --------
    for (int i = tid; i < 64 * 512; i += 512) {
        int jj = i >> 9, k = i & 511;
        ((float*)wS)[((k >> 1) * 64 + jj) * 2 + (k & 1)] = huw[(size_t)(jjbase + jj) * HH + k];
    }
    if (tid < 256) zup[tid] = ((const ull*)ztu_g)[tid];
    else           rup[tid - 256] = ((const ull*)rtu_g)[tid - 256];
    for (int i = tid; i < 1024; i += 512) {
        hpb[i] = ((const ull*)hidden)[(size_t)(grp * 4 + (i & 3)) * 256 + (i >> 2)];
    }
    if (tid < 64) hub[tid] = hub_g[jjbase + tid];
    float zub = ztub[0], rub = rtub[0];

    int lane = tid & 31;
    int warp = tid >> 5;
    int jjp  = lane;            // jj pair 0..31
    int ks   = warp;            // k segment 0..15
    int gate = warp & 1;
    int ks8  = warp >> 1;
    int jj4  = tid & 63;
    int b4   = (tid >> 6) & 3;

    // precompute remote fan-out addresses (buffer 0 target)
    unsigned rbase[8];
    {
        unsigned loc0 = smem_u32(&hpb[((jjbase + jj4) >> 1) * 4 + b4]);
#pragma unroll
        for (int r = 0; r < 8; r++)
            asm("mapa.shared::cluster.u32 %0, %1, %2;" : "=r"(rbase[r]) : "r"(loc0), "r"(r));
    }

    // prefetch step-0 inputs
    size_t obase = 0;
    float xnv = 0.f, xzv = 0.f, xrv = 0.f;
    if (tid < 256) {
        obase = (size_t)(grp * 4 + b4) * HH + jjbase + jj4;
        xnv = out[obase];
        xzv = g_xz[grp * 4 + b4];
        xrv = g_xr[grp * 4 + b4];
    }

    __syncthreads();
    asm volatile("barrier.cluster.arrive.aligned;" ::: "memory");
    asm volatile("barrier.cluster.wait.aligned;" ::: "memory");

    for (int t = 0; t < TT; t++) {
        int s = t & 1, sf = s ^ 1;
        const ull* hp = hpb + s * 1024;

        // -------- gates: 16 warps = gate(2) x ks8(8), 64 k (32 kp) each --------
        {
            int kp = ks8 * 32 + lane;
            ull u = (gate ? rup : zup)[kp];
            QU A, B;
            A.q = *(const uint4*)(hp + kp * 4);
            B.q = *(const uint4*)(hp + kp * 4 + 2);
            ull a0 = 0, a1 = 0, a2 = 0, a3 = 0;
            fma2(a0, A.u[0], u);
            fma2(a1, A.u[1], u);
            fma2(a2, B.u[0], u);
            fma2(a3, B.u[1], u);
            U64F2 c0, c1, c2, c3;
            c0.u = a0; c1.u = a1; c2.u = a2; c3.u = a3;
            float s0 = c0.f.x + c0.f.y, s1 = c1.f.x + c1.f.y;
            float s2 = c2.f.x + c2.f.y, s3 = c3.f.x + c3.f.y;
#pragma unroll
            for (int off = 16; off >= 1; off >>= 1) {
                s0 += __shfl_xor_sync(0xffffffffu, s0, off);
                s1 += __shfl_xor_sync(0xffffffffu, s1, off);
                s2 += __shfl_xor_sync(0xffffffffu, s2, off);
                s3 += __shfl_xor_sync(0xffffffffu, s3, off);
            }
            if (lane == 0) ((float4*)zrpf)[gate * 8 + ks8] = make_float4(s0, s1, s2, s3);
        }

        // -------- main dot: k-pair f32x2, 2 jj x 4 b per thread --------
        {
            const ull* wp = wS + ks * 1024 + jjp * 2;
            const ull* hq = hp + ks * 64;
            ull a00 = 0, a01v = 0, a02 = 0, a03 = 0;
            ull a10 = 0, a11v = 0, a12 = 0, a13 = 0;
#pragma unroll
            for (int i = 0; i < 16; i++) {
                QU Wq, Ha, Hb;
                Wq.q = *(const uint4*)(wp + i * 64);
                Ha.q = *(const uint4*)(hq + i * 4);
                Hb.q = *(const uint4*)(hq + i * 4 + 2);
                fma2(a00,  Wq.u[0], Ha.u[0]);
                fma2(a01v, Wq.u[0], Ha.u[1]);
                fma2(a02,  Wq.u[0], Hb.u[0]);
                fma2(a03,  Wq.u[0], Hb.u[1]);
                fma2(a10,  Wq.u[1], Ha.u[0]);
                fma2(a11v, Wq.u[1], Ha.u[1]);
                fma2(a12,  Wq.u[1], Hb.u[0]);
                fma2(a13,  Wq.u[1], Hb.u[1]);
            }
            U64F2 u0, u1;
            float2* pp = (float2*)part;
            u0.u = a00;  u1.u = a10;
            pp[ks * 128 + 0 * 32 + jjp] = make_float2(u0.f.x + u0.f.y, u1.f.x + u1.f.y);
            u0.u = a01v; u1.u = a11v;
            pp[ks * 128 + 1 * 32 + jjp] = make_float2(u0.f.x + u0.f.y, u1.f.x + u1.f.y);
            u0.u = a02;  u1.u = a12;
            pp[ks * 128 + 2 * 32 + jjp] = make_float2(u0.f.x + u0.f.y, u1.f.x + u1.f.y);
            u0.u = a03;  u1.u = a13;
            pp[ks * 128 + 3 * 32 + jjp] = make_float2(u0.f.x + u0.f.y, u1.f.x + u1.f.y);
        }
        __syncthreads();

        // -------- finish: reduce + gates + write + fan-out + next prefetch --------
        if (tid < 256) {
            float ssum = 0.f;
#pragma unroll
            for (int ki = 0; ki < 16; ki++) ssum += part[ki * 256 + b4 * 64 + jj4];
            float gz = 0.f, gr = 0.f;
#pragma unroll
            for (int k8 = 0; k8 < 8; k8++) {
                gz += zrpf[k8 * 4 + b4];
                gr += zrpf[32 + k8 * 4 + b4];
            }
            float zt = sigmoid_fast(xzv + gz + zub);
            float rt = sigmoid_fast(xrv + gr + rub);
            float nt = tanh_fast(fmaf(ssum + hub[jj4], rt, xnv));
            U64F2 hold2; hold2.u = hp[((jjbase + jj4) >> 1) * 4 + b4];
            float hold = (jj4 & 1) ? hold2.f.y : hold2.f.x;
            float hn = (1.f - zt) * nt + zt * hold;

            if (t < TT - 1) {
                // fan-out first (latency-critical), then local stores
                float hn1 = __shfl_down_sync(0xffffffffu, hn, 1);
                if ((jj4 & 1) == 0) {
                    ull v = pack2(hn, hn1);
                    unsigned boff = (unsigned)sf * 8192u;
#pragma unroll
                    for (int r = 0; r < 8; r++) {
                        asm volatile("st.shared::cluster.b64 [%0], %1;"
                                     :: "r"(rbase[r] + boff), "l"(v) : "memory");
                    }
                }
                out[obase] = hn;
                // prefetch next step inputs (hidden under the barrier)
                obase += (size_t)BB * HH;
                xnv = out[obase];
                xzv = g_xz[(t + 1) * BB + grp * 4 + b4];
                xrv = g_xr[(t + 1) * BB + grp * 4 + b4];
            } else {
                out[obase] = hn;
                if (tail >= BB * HH)
                    out[(size_t)TT * BB * HH + (size_t)(grp * 4 + b4) * HH + jjbase + jj4] = hn;
            }
        }

        // cluster barrier: orders remote stores, subsumes __syncthreads
        asm volatile("barrier.cluster.arrive.release.aligned;" ::: "memory");
        asm volatile("barrier.cluster.wait.acquire.aligned;" ::: "memory");
    }
}

// ---------------- launch ----------------
extern "C" void kernel_launch(void* const* d_in, const int* in_sizes, int n_in,
                              void* d_out, int out_size) {
    const float* input  = (const float*)d_in[0];
    const float* hidden = (const float*)d_in[1];
    const float* zt_w_w = (const float*)d_in[2];
    const float* zt_w_b = (const float*)d_in[3];
    const float* zt_u_w = (const float*)d_in[4];
    const float* zt_u_b = (const float*)d_in[5];
    const float* rt_w_w = (const float*)d_in[6];
    const float* rt_w_b = (const float*)d_in[7];
    const float* rt_u_w = (const float*)d_in[8];
    const float* rt_u_b = (const float*)d_in[9];
    const float* h_w_w  = (const float*)d_in[10];
    const float* h_w_b  = (const float*)d_in[11];
    const float* h_u_w  = (const float*)d_in[12];
    const float* h_u_b  = (const float*)d_in[13];
    float* out = (float*)d_out;

    int tail = out_size - TT * BB * HH;

    gate_pre_kernel<<<TT * BB / 8, 256>>>(input, zt_w_w, zt_w_b, rt_w_w, rt_w_b);

    {
        dim3 grid(TT * BB / 128, HH / 64);
        xn_gemm_kernel<<<grid, 256>>>(input, h_w_w, h_w_b, out);
    }

    static int smem_set = 0;
    if (!smem_set) {
        cudaFuncSetAttribute(scan_kernel, cudaFuncAttributeMaxDynamicSharedMemorySize, SC_SMEM);
        smem_set = 1;
    }
    scan_kernel<<<128, 512, SC_SMEM>>>(hidden, zt_u_w, zt_u_b, rt_u_w, rt_u_b,
                                       h_u_w, h_u_b, out, tail);
}

// round 6
// speedup vs baseline: 1.4354x; 1.4354x over previous
#include <cuda_runtime.h>
#include <cuda_bf16.h>
#include <math.h>

// Problem dims
#define TT 512
#define BB 64
#define II 512
#define HH 512

// ---------------- device scratch ----------------
__device__ float g_xz[TT * BB];   // [t][b] includes zt_w_b
__device__ float g_xr[TT * BB];   // [t][b] includes rt_w_b

// ---------------- helpers ----------------
typedef unsigned long long ull;
union U64F2 { ull u; float2 f; };
union QU    { uint4 q; ull u[2]; };

__device__ __forceinline__ void fma2(ull& d, ull a, ull b) {
    asm("fma.rn.f32x2 %0, %1, %2, %0;" : "+l"(d) : "l"(a), "l"(b));
}
__device__ __forceinline__ ull pack2(float lo, float hi) {
    ull r; asm("mov.b64 %0, {%1, %2};" : "=l"(r) : "f"(lo), "f"(hi)); return r;
}
__device__ __forceinline__ float sigmoid_fast(float x) {
    float e, r;
    asm("ex2.approx.f32 %0, %1;" : "=f"(e) : "f"(-1.4426950408889634f * x));
    asm("rcp.approx.f32 %0, %1;" : "=f"(r) : "f"(1.0f + e));
    return r;
}
__device__ __forceinline__ float tanh_fast(float x) {
    float e, r;
    asm("ex2.approx.f32 %0, %1;" : "=f"(e) : "f"(-2.8853900817779268f * x));
    asm("rcp.approx.f32 %0, %1;" : "=f"(r) : "f"(1.0f + e));
    return fmaf(2.0f, r, -1.0f);
}
__device__ __forceinline__ unsigned smem_u32(const void* p) {
    return (unsigned)__cvta_generic_to_shared(p);
}

// ---------------- kernel 1: gate input projections xz, xr ----------------
__global__ void gate_pre_kernel(const float* __restrict__ in,
                                const float* __restrict__ zw, const float* __restrict__ zb,
                                const float* __restrict__ rw, const float* __restrict__ rb) {
    int row  = blockIdx.x * 8 + (threadIdx.x >> 5);
    int lane = threadIdx.x & 31;
    const float4* a4 = (const float4*)(in + (size_t)row * II);
    const float4* z4 = (const float4*)zw;
    const float4* r4 = (const float4*)rw;
    float az = 0.f, ar = 0.f;
#pragma unroll 4
    for (int i = lane; i < II / 4; i += 32) {
        float4 v = a4[i];
        float4 z = z4[i];
        float4 r = r4[i];
        az += v.x * z.x + v.y * z.y + v.z * z.z + v.w * z.w;
        ar += v.x * r.x + v.y * r.y + v.z * r.z + v.w * r.w;
    }
#pragma unroll
    for (int off = 16; off >= 1; off >>= 1) {
        az += __shfl_xor_sync(0xffffffffu, az, off);
        ar += __shfl_xor_sync(0xffffffffu, ar, off);
    }
    if (lane == 0) {
        g_xz[row] = az + zb[0];
        g_xr[row] = ar + rb[0];
    }
}

// ---------------- kernel 2: xn GEMM, k-pair f32x2, conflict-free smem ----
__global__ __launch_bounds__(256) void xn_gemm_kernel(const float* __restrict__ A,
                                                      const float* __restrict__ W,
                                                      const float* __restrict__ bias,
                                                      float* __restrict__ C) {
    __shared__ ull As2[16][130];   // [kp][m]
    __shared__ ull Ws2[16][66];    // [kp][n]

    int tid  = threadIdx.x;
    int ncol = tid & 7;
    int mrow = tid >> 3;
    int nc2  = ncol * 2;
    int bm   = blockIdx.x * 128;
    int bn   = blockIdx.y * 64;

    ull acc[4][8];
#pragma unroll
    for (int i = 0; i < 4; i++)
#pragma unroll
        for (int j = 0; j < 8; j++) acc[i][j] = 0ull;

    const float4* A4 = (const float4*)A;
    const float4* W4 = (const float4*)W;

    float4 pa[4], pw[2];
#pragma unroll
    for (int q = 0; q < 4; q++) {
        int s = tid + q * 256;
        pa[q] = A4[(size_t)(bm + (s >> 3)) * 128 + (s & 7)];
    }
#pragma unroll
    for (int q = 0; q < 2; q++) {
        int s = tid + q * 256;
        pw[q] = W4[(size_t)(bn + (s >> 3)) * 128 + (s & 7)];
    }

    for (int blk = 0; blk < 16; blk++) {
#pragma unroll
        for (int q = 0; q < 4; q++) {
            int s = tid + q * 256;
            int m = s >> 3, f4 = s & 7;
            As2[f4 * 2][m]     = pack2(pa[q].x, pa[q].y);
            As2[f4 * 2 + 1][m] = pack2(pa[q].z, pa[q].w);
        }
#pragma unroll
        for (int q = 0; q < 2; q++) {
            int s = tid + q * 256;
            int n = s >> 3, f4 = s & 7;
            Ws2[f4 * 2][n]     = pack2(pw[q].x, pw[q].y);
            Ws2[f4 * 2 + 1][n] = pack2(pw[q].z, pw[q].w);
        }
        __syncthreads();
        if (blk < 15) {
            int kq = (blk + 1) * 8;
#pragma unroll
            for (int q = 0; q < 4; q++) {
                int s = tid + q * 256;
                pa[q] = A4[(size_t)(bm + (s >> 3)) * 128 + kq + (s & 7)];
            }
#pragma unroll
            for (int q = 0; q < 2; q++) {
                int s = tid + q * 256;
                pw[q] = W4[(size_t)(bn + (s >> 3)) * 128 + kq + (s & 7)];
            }
        }
#pragma unroll
        for (int kp = 0; kp < 16; kp++) {
            QU a01, a23, w0, w1, w2, w3;
            a01.q = *(const uint4*)&As2[kp][mrow * 4];
            a23.q = *(const uint4*)&As2[kp][mrow * 4 + 2];
            w0.q  = *(const uint4*)&Ws2[kp][nc2];
            w1.q  = *(const uint4*)&Ws2[kp][nc2 + 16];
            w2.q  = *(const uint4*)&Ws2[kp][nc2 + 32];
            w3.q  = *(const uint4*)&Ws2[kp][nc2 + 48];
            ull av[4] = {a01.u[0], a01.u[1], a23.u[0], a23.u[1]};
            ull wv[8] = {w0.u[0], w0.u[1], w1.u[0], w1.u[1],
                         w2.u[0], w2.u[1], w3.u[0], w3.u[1]};
#pragma unroll
            for (int i = 0; i < 4; i++)
#pragma unroll
                for (int j = 0; j < 8; j++) fma2(acc[i][j], av[i], wv[j]);
        }
        __syncthreads();
    }

    float2 bq[4];
#pragma unroll
    for (int q = 0; q < 4; q++)
        bq[q] = ((const float2*)bias)[(bn >> 1) + (nc2 >> 1) + q * 8];

#pragma unroll
    for (int mi = 0; mi < 4; mi++) {
        int m = bm + mrow * 4 + mi;
#pragma unroll
        for (int q = 0; q < 4; q++) {
            U64F2 c0, c1;
            c0.u = acc[mi][q * 2];
            c1.u = acc[mi][q * 2 + 1];
            float2 o;
            o.x = c0.f.x + c0.f.y + bq[q].x;
            o.y = c1.f.x + c1.f.y + bq[q].y;
            ((float2*)C)[(size_t)m * 256 + (bn >> 1) + (nc2 >> 1) + q * 8] = o;
        }
    }
}

// ---------------- kernel 3: recurrent scan ----------------
// 16 clusters x 8 CTAs x 512 threads. NO per-step cluster barrier.
// h exchange: each CTA stages its 1KB chunk, then 8 threads issue 8x
// cp.async.bulk (shared::cta -> shared::cluster) with mbarrier complete_tx
// into each peer's double-buffered h region. Consumer: thread0 posts
// expect_tx(8KB) and parity-waits; __syncthreads releases the CTA.
#define WS_OFF   0                        // ull[256][64]  = 128KB
#define HP_OFF   131072                   // ull[2][1024]  = 16KB
#define PART_OFF (HP_OFF + 16384)         // float[16][4][64] = 16KB
#define ZRP_OFF  (PART_OFF + 16384)       // float[64]
#define ZUP_OFF  (ZRP_OFF + 256)          // ull[256]
#define RUP_OFF  (ZUP_OFF + 2048)         // ull[256]
#define HUB_OFF  (RUP_OFF + 2048)         // float[64]
#define HST_OFF  (HUB_OFF + 256)          // ull[128] staging = 1KB
#define MBAR_OFF (HST_OFF + 1024)         // 2 x b64
#define SC_SMEM  (MBAR_OFF + 64)

extern __shared__ char sc_smem[];

__global__ void __cluster_dims__(8, 1, 1) __launch_bounds__(512, 1)
scan_kernel(const float* __restrict__ hidden,
            const float* __restrict__ ztu_g, const float* __restrict__ ztub,
            const float* __restrict__ rtu_g, const float* __restrict__ rtub,
            const float* __restrict__ huw, const float* __restrict__ hub_g,
            float* __restrict__ out, int tail) {
    ull*   wS   = (ull*)(sc_smem + WS_OFF);
    ull*   hpb  = (ull*)(sc_smem + HP_OFF);
    float* part = (float*)(sc_smem + PART_OFF);
    float* zrpf = (float*)(sc_smem + ZRP_OFF);
    ull*   zup  = (ull*)(sc_smem + ZUP_OFF);
    ull*   rup  = (ull*)(sc_smem + RUP_OFF);
    float* hub  = (float*)(sc_smem + HUB_OFF);
    ull*   hst  = (ull*)(sc_smem + HST_OFF);

    int tid    = threadIdx.x;
    int rank   = blockIdx.x & 7;
    int grp    = blockIdx.x >> 3;
    int jjbase = rank * 64;
    unsigned mbase = smem_u32(sc_smem + MBAR_OFF);
    unsigned hst_a = smem_u32(hst);

    // -------- prologue --------
    for (int i = tid; i < 64 * 512; i += 512) {
        int jj = i >> 9, k = i & 511;
        ((float*)wS)[((k >> 1) * 64 + jj) * 2 + (k & 1)] = huw[(size_t)(jjbase + jj) * HH + k];
    }
    if (tid < 256) zup[tid] = ((const ull*)ztu_g)[tid];
    else           rup[tid - 256] = ((const ull*)rtu_g)[tid - 256];
    for (int i = tid; i < 1024; i += 512) {
        hpb[i] = ((const ull*)hidden)[(size_t)(grp * 4 + (i & 3)) * 256 + (i >> 2)];
    }
    if (tid < 64) hub[tid] = hub_g[jjbase + tid];
    float zub = ztub[0], rub = rtub[0];
    if (tid == 0) {
        asm volatile("mbarrier.init.shared.b64 [%0], %1;" :: "r"(mbase), "r"(1) : "memory");
        asm volatile("mbarrier.init.shared.b64 [%0], %1;" :: "r"(mbase + 8), "r"(1) : "memory");
    }

    int lane = tid & 31;
    int warp = tid >> 5;
    int jjp  = lane;            // jj pair 0..31
    int ks   = warp;            // k segment 0..15
    int gate = warp & 1;
    int ks8  = warp >> 1;
    int jj4  = tid & 63;
    int b4   = (tid >> 6) & 3;

    // per-lane remote targets (lanes 0..7 -> peer ranks 0..7)
    unsigned dst_r = 0, mb_r = 0;
    if (tid < 8) {
        unsigned loc = smem_u32(&hpb[jjbase * 2]);    // this CTA's chunk offset in buffer 0
        asm("mapa.shared::cluster.u32 %0, %1, %2;" : "=r"(dst_r) : "r"(loc), "r"(tid));
        asm("mapa.shared::cluster.u32 %0, %1, %2;" : "=r"(mb_r) : "r"(mbase), "r"(tid));
    }

    // prefetch step-0 inputs
    size_t obase = 0;
    float xnv = 0.f, xzv = 0.f, xrv = 0.f;
    if (tid < 256) {
        obase = (size_t)(grp * 4 + b4) * HH + jjbase + jj4;
        xnv = out[obase];
        xzv = g_xz[grp * 4 + b4];
        xrv = g_xr[grp * 4 + b4];
    }

    __syncthreads();
    // one-time: mbarrier inits visible cluster-wide before any remote complete_tx
    asm volatile("barrier.cluster.arrive.aligned;" ::: "memory");
    asm volatile("barrier.cluster.wait.aligned;" ::: "memory");

    int par0 = 0, par1 = 0;

    for (int t = 0; t < TT; t++) {
        int s = t & 1, sf = s ^ 1;

        // arm next-step barrier (tx counts are cumulative; order-safe)
        if (tid == 0 && t < TT - 1) {
            asm volatile("mbarrier.arrive.expect_tx.shared::cta.b64 _, [%0], %1;"
                         :: "r"(mbase + sf * 8), "r"(8192) : "memory");
        }
        // wait for this step's h (thread0 only, then release CTA)
        if (t > 0) {
            if (tid == 0) {
                int ph = s ? par1 : par0;
                unsigned done = 0;
                while (!done) {
                    asm volatile(
                        "{\n\t.reg .pred p;\n\t"
                        "mbarrier.try_wait.parity.acquire.cta.shared::cta.b64 p, [%1], %2, 0x989680;\n\t"
                        "selp.b32 %0, 1, 0, p;\n\t}"
                        : "=r"(done) : "r"(mbase + s * 8), "r"(ph) : "memory");
                }
            }
            if (s) par1 ^= 1; else par0 ^= 1;
            __syncthreads();
        }

        const ull* hp = hpb + s * 1024;

        // -------- gates: 16 warps = gate(2) x ks8(8), 64 k (32 kp) each --------
        {
            int kp = ks8 * 32 + lane;
            ull u = (gate ? rup : zup)[kp];
            QU A, B;
            A.q = *(const uint4*)(hp + kp * 4);
            B.q = *(const uint4*)(hp + kp * 4 + 2);
            ull a0 = 0, a1 = 0, a2 = 0, a3 = 0;
            fma2(a0, A.u[0], u);
            fma2(a1, A.u[1], u);
            fma2(a2, B.u[0], u);
            fma2(a3, B.u[1], u);
            U64F2 c0, c1, c2, c3;
            c0.u = a0; c1.u = a1; c2.u = a2; c3.u = a3;
            float s0 = c0.f.x + c0.f.y, s1 = c1.f.x + c1.f.y;
            float s2 = c2.f.x + c2.f.y, s3 = c3.f.x + c3.f.y;
#pragma unroll
            for (int off = 16; off >= 1; off >>= 1) {
                s0 += __shfl_xor_sync(0xffffffffu, s0, off);
                s1 += __shfl_xor_sync(0xffffffffu, s1, off);
                s2 += __shfl_xor_sync(0xffffffffu, s2, off);
                s3 += __shfl_xor_sync(0xffffffffu, s3, off);
            }
            if (lane == 0) ((float4*)zrpf)[gate * 8 + ks8] = make_float4(s0, s1, s2, s3);
        }

        // -------- main dot: k-pair f32x2, 2 jj x 4 b per thread --------
        {
            const ull* wp = wS + ks * 1024 + jjp * 2;
            const ull* hq = hp + ks * 64;
            ull a00 = 0, a01v = 0, a02 = 0, a03 = 0;
            ull a10 = 0, a11v = 0, a12 = 0, a13 = 0;
#pragma unroll
            for (int i = 0; i < 16; i++) {
                QU Wq, Ha, Hb;
                Wq.q = *(const uint4*)(wp + i * 64);
                Ha.q = *(const uint4*)(hq + i * 4);
                Hb.q = *(const uint4*)(hq + i * 4 + 2);
                fma2(a00,  Wq.u[0], Ha.u[0]);
                fma2(a01v, Wq.u[0], Ha.u[1]);
                fma2(a02,  Wq.u[0], Hb.u[0]);
                fma2(a03,  Wq.u[0], Hb.u[1]);
                fma2(a10,  Wq.u[1], Ha.u[0]);
                fma2(a11v, Wq.u[1], Ha.u[1]);
                fma2(a12,  Wq.u[1], Hb.u[0]);
                fma2(a13,  Wq.u[1], Hb.u[1]);
            }
            U64F2 u0, u1;
            float2* pp = (float2*)part;
            u0.u = a00;  u1.u = a10;
            pp[ks * 128 + 0 * 32 + jjp] = make_float2(u0.f.x + u0.f.y, u1.f.x + u1.f.y);
            u0.u = a01v; u1.u = a11v;
            pp[ks * 128 + 1 * 32 + jjp] = make_float2(u0.f.x + u0.f.y, u1.f.x + u1.f.y);
            u0.u = a02;  u1.u = a12;
            pp[ks * 128 + 2 * 32 + jjp] = make_float2(u0.f.x + u0.f.y, u1.f.x + u1.f.y);
            u0.u = a03;  u1.u = a13;
            pp[ks * 128 + 3 * 32 + jjp] = make_float2(u0.f.x + u0.f.y, u1.f.x + u1.f.y);
        }
        __syncthreads();

        // -------- finish: reduce + gates + write + stage + next prefetch --------
        if (tid < 256) {
            float ssum = 0.f;
#pragma unroll
            for (int ki = 0; ki < 16; ki++) ssum += part[ki * 256 + b4 * 64 + jj4];
            float gz = 0.f, gr = 0.f;
#pragma unroll
            for (int k8 = 0; k8 < 8; k8++) {
                gz += zrpf[k8 * 4 + b4];
                gr += zrpf[32 + k8 * 4 + b4];
            }
            float zt = sigmoid_fast(xzv + gz + zub);
            float rt = sigmoid_fast(xrv + gr + rub);
            float nt = tanh_fast(fmaf(ssum + hub[jj4], rt, xnv));
            U64F2 hold2; hold2.u = hp[((jjbase + jj4) >> 1) * 4 + b4];
            float hold = (jj4 & 1) ? hold2.f.y : hold2.f.x;
            float hn = (1.f - zt) * nt + zt * hold;

            out[obase] = hn;
            float hn1 = __shfl_down_sync(0xffffffffu, hn, 1);
            if ((jj4 & 1) == 0) hst[(jj4 >> 1) * 4 + b4] = pack2(hn, hn1);

            if (t < TT - 1) {
                // prefetch next step inputs
                obase += (size_t)BB * HH;
                xnv = out[obase];
                xzv = g_xz[(t + 1) * BB + grp * 4 + b4];
                xrv = g_xr[(t + 1) * BB + grp * 4 + b4];
            } else if (tail >= BB * HH) {
                out[(size_t)TT * BB * HH + (size_t)(grp * 4 + b4) * HH + jjbase + jj4] = hn;
            }
        }
        __syncthreads();

        // -------- fan-out: 8 bulk copies (1KB each) to all peers --------
        if (t < TT - 1 && tid < 8) {
            asm volatile("fence.proxy.async.shared::cta;" ::: "memory");
            unsigned dst = dst_r + (unsigned)sf * 8192u;
            unsigned mb  = mb_r + (unsigned)sf * 8u;
            asm volatile(
                "cp.async.bulk.shared::cluster.shared::cta.mbarrier::complete_tx::bytes "
                "[%0], [%1], %2, [%3];"
                :: "r"(dst), "r"(hst_a), "r"(1024u), "r"(mb) : "memory");
        }
    }

    // teardown: no CTA leaves while peers may still target its smem
    asm volatile("barrier.cluster.arrive.aligned;" ::: "memory");
    asm volatile("barrier.cluster.wait.aligned;" ::: "memory");
}

// ---------------- launch ----------------
extern "C" void kernel_launch(void* const* d_in, const int* in_sizes, int n_in,
                              void* d_out, int out_size) {
    const float* input  = (const float*)d_in[0];
    const float* hidden = (const float*)d_in[1];
    const float* zt_w_w = (const float*)d_in[2];
    const float* zt_w_b = (const float*)d_in[3];
    const float* zt_u_w = (const float*)d_in[4];
    const float* zt_u_b = (const float*)d_in[5];
    const float* rt_w_w = (const float*)d_in[6];
    const float* rt_w_b = (const float*)d_in[7];
    const float* rt_u_w = (const float*)d_in[8];
    const float* rt_u_b = (const float*)d_in[9];
    const float* h_w_w  = (const float*)d_in[10];
    const float* h_w_b  = (const float*)d_in[11];
    const float* h_u_w  = (const float*)d_in[12];
    const float* h_u_b  = (const float*)d_in[13];
    float* out = (float*)d_out;

    int tail = out_size - TT * BB * HH;

    gate_pre_kernel<<<TT * BB / 8, 256>>>(input, zt_w_w, zt_w_b, rt_w_w, rt_w_b);

    {
        dim3 grid(TT * BB / 128, HH / 64);
        xn_gemm_kernel<<<grid, 256>>>(input, h_w_w, h_w_b, out);
    }

    static int smem_set = 0;
    if (!smem_set) {
        cudaFuncSetAttribute(scan_kernel, cudaFuncAttributeMaxDynamicSharedMemorySize, SC_SMEM);
        smem_set = 1;
    }
    scan_kernel<<<128, 512, SC_SMEM>>>(hidden, zt_u_w, zt_u_b, rt_u_w, rt_u_b,
                                       h_u_w, h_u_b, out, tail);
}